// round 10
// baseline (speedup 1.0000x reference)
#include <cuda_runtime.h>
#include <cfloat>
#include <cstddef>

#define BATCH 4
#define NPTS  1024
#define NROWS (BATCH*NPTS)
#define KNN   20
#define BNS   0.99999500003749968f   // 1/sqrt(1+1e-5)

// ---------------- scratch (static device globals; no allocation) ----------------
__device__ float g_xc[NROWS * 960];              // concat feature buffer [x1|x2|x3|x4]
__device__ float g_ye[NROWS * KNN * 512];        // per-edge conv output (ld = O)
__device__ float g_q[NROWS * 512];               // conv5 out
__device__ float g_sq[NROWS];                    // squared norms
__device__ int   g_idx[NROWS * KNN];             // knn indices (within-batch)
__device__ float g_feat[BATCH * 512];            // global max-pooled features

// ---------------- squared norms, small C: strict sequential ----------------
__global__ void sqnorm_kernel(const float* __restrict__ X, int ld, int C,
                              float* __restrict__ sq) {
    int i = blockIdx.x * blockDim.x + threadIdx.x;
    if (i >= NROWS) return;
    const float* r = X + (size_t)i * ld;
    float s = 0.f;
    for (int c = 0; c < C; c++) {
        float p = __fmul_rn(r[c], r[c]);
        s = __fadd_rn(s, p);
    }
    sq[i] = s;
}

// ---------------- squared norms, C>=64: XLA GPU row-reduce emulation --------------
// warp per row; lane l sums x[l], x[l+32], ... (ascending, fma);
// then shfl_down tree with offsets 16,8,4,2,1 (XLA warp reduce shape).
__global__ void sqnorm_warp_kernel(const float* __restrict__ X, int ld, int C,
                                   float* __restrict__ sq) {
    int gt = blockIdx.x * blockDim.x + threadIdx.x;
    int warp = gt >> 5;
    int lane = gt & 31;
    if (warp >= NROWS) return;
    const float* r = X + (size_t)warp * ld;
    float s = 0.f;
    for (int c = lane; c < C; c += 32) s = fmaf(r[c], r[c], s);
    #pragma unroll
    for (int off = 16; off > 0; off >>= 1)
        s = __fadd_rn(s, __shfl_down_sync(0xffffffffu, s, off));
    if (lane == 0) sq[warp] = s;
}

// ---------------- knn: one block per (b,n) row ----------------
// dot: ascending FMA (cublas sgemm order); d = ((2*dot - sqn) - sqm), strict.
__global__ __launch_bounds__(256) void knn_kernel(const float* __restrict__ X,
                                                  int ld, int C,
                                                  const float* __restrict__ sq,
                                                  int* __restrict__ idx) {
    int row = blockIdx.x;               // b*1024 + n
    int b = row >> 10;
    int n = row & 1023;
    const float* base = X + (size_t)b * NPTS * ld;

    __shared__ __align__(16) float ctr[256];
    __shared__ float d[NPTS];
    __shared__ float rv[256];
    __shared__ int   ri[256];

    int t = threadIdx.x;
    for (int c = t; c < C; c += 256) ctr[c] = base[(size_t)n * ld + c];
    __syncthreads();

    float sqn = sq[row];

    if ((C & 3) == 0 && (ld & 3) == 0) {
        int C4 = C >> 2;
        for (int m = t; m < NPTS; m += 256) {
            const float4* xm = (const float4*)(base + (size_t)m * ld);
            const float4* cc = (const float4*)ctr;
            float s = 0.f;
            #pragma unroll 4
            for (int c = 0; c < C4; c++) {
                float4 v = xm[c], u = cc[c];
                s = fmaf(v.x, u.x, s);
                s = fmaf(v.y, u.y, s);
                s = fmaf(v.z, u.z, s);
                s = fmaf(v.w, u.w, s);
            }
            float dd = __fmul_rn(2.0f, s);
            dd = __fsub_rn(dd, sqn);
            dd = __fsub_rn(dd, sq[(b << 10) + m]);
            d[m] = dd;
        }
    } else {
        for (int m = t; m < NPTS; m += 256) {
            const float* xm = base + (size_t)m * ld;
            float s = 0.f;
            for (int c = 0; c < C; c++) {
                float p = __fmul_rn(xm[c], ctr[c]);
                s = __fadd_rn(s, p);
            }
            float dd = __fmul_rn(2.0f, s);
            dd = __fsub_rn(dd, sqn);
            dd = __fsub_rn(dd, sq[(b << 10) + m]);
            d[m] = dd;
        }
    }
    __syncthreads();

    // 20 rounds of block argmax (tie-break: smallest index, matches lax.top_k)
    for (int r = 0; r < KNN; r++) {
        float bv = -FLT_MAX; int bi = NPTS;
        for (int m = t; m < NPTS; m += 256) {
            float v = d[m];
            if (v > bv || (v == bv && m < bi)) { bv = v; bi = m; }
        }
        rv[t] = bv; ri[t] = bi;
        __syncthreads();
        for (int s = 128; s > 0; s >>= 1) {
            if (t < s) {
                float v2 = rv[t + s]; int i2 = ri[t + s];
                if (v2 > rv[t] || (v2 == rv[t] && i2 < ri[t])) { rv[t] = v2; ri[t] = i2; }
            }
            __syncthreads();
        }
        if (t == 0) {
            idx[row * KNN + r] = ri[0];
            d[ri[0]] = -FLT_MAX;
        }
        __syncthreads();
    }
}

// ---------------- fp32 SGEMM, ascending-k single accumulator --------------------
// mode 0: a[m,k] = A[m*lda + k]
// mode 1 (edge einsum): m is an edge id; for k <  Chalf: a = fl(A[nbr,k] - A[ctr,k])
//                                         for k >= Chalf: a = A[ctr, k-Chalf]
#define BM 128
#define BN_ 128
#define BK 16

__global__ __launch_bounds__(256) void sgemm_kernel(
    const float* __restrict__ A, int lda,
    const float* __restrict__ Bw, int ldb,
    float* __restrict__ Cc, int ldc,
    int Nn, int Kk, int Chalf,
    int mode, const int* __restrict__ idx,
    int epi, const float* __restrict__ gs, const float* __restrict__ bs) {

    __shared__ __align__(16) float As[BK][BM + 4];
    __shared__ __align__(16) float Bs[BK][BN_ + 4];
    __shared__ int nbr_s[BM];
    __shared__ int ctr_s[BM];

    int t  = threadIdx.x;
    int tx = t & 15, ty = t >> 4;
    int m0 = blockIdx.y * BM;
    int n0 = blockIdx.x * BN_;

    if (mode == 1) {
        if (t < BM) {
            int edge = m0 + t;
            int row = edge / KNN;          // global point row 0..4095
            int b = row >> 10;
            nbr_s[t] = (b << 10) + idx[edge];
            ctr_s[t] = row;
        }
        __syncthreads();
    }

    float acc[8][8];
    #pragma unroll
    for (int i = 0; i < 8; i++)
        #pragma unroll
        for (int j = 0; j < 8; j++) acc[i][j] = 0.f;

    for (int k0 = 0; k0 < Kk; k0 += BK) {
        #pragma unroll
        for (int u = 0; u < 8; u++) {
            int e = t + u * 256;          // 2048 elems
            int i = e >> 4, k = e & 15;
            int gk = k0 + k;
            float v = 0.f;
            if (gk < Kk) {
                if (mode == 1) {
                    if (gk < Chalf)
                        v = __fsub_rn(A[(size_t)nbr_s[i] * lda + gk],
                                      A[(size_t)ctr_s[i] * lda + gk]);
                    else
                        v = A[(size_t)ctr_s[i] * lda + (gk - Chalf)];
                } else {
                    v = A[(size_t)(m0 + i) * lda + gk];
                }
            }
            As[k][i] = v;
        }
        #pragma unroll
        for (int u = 0; u < 8; u++) {
            int e = t + u * 256;
            int j = e >> 4, k = e & 15;
            int gk = k0 + k;
            float v = 0.f;
            if (gk < Kk && (n0 + j) < Nn)
                v = Bw[(size_t)(n0 + j) * ldb + gk];
            Bs[k][j] = v;
        }
        __syncthreads();

        #pragma unroll
        for (int k = 0; k < BK; k++) {     // ascending k: preserves sgemm order
            float a[8], b[8];
            *(float4*)&a[0] = *(const float4*)&As[k][ty * 8];
            *(float4*)&a[4] = *(const float4*)&As[k][ty * 8 + 4];
            *(float4*)&b[0] = *(const float4*)&Bs[k][tx * 8];
            *(float4*)&b[4] = *(const float4*)&Bs[k][tx * 8 + 4];
            #pragma unroll
            for (int i = 0; i < 8; i++)
                #pragma unroll
                for (int j = 0; j < 8; j++)
                    acc[i][j] = fmaf(a[i], b[j], acc[i][j]);
        }
        __syncthreads();
    }

    #pragma unroll
    for (int i = 0; i < 8; i++) {
        int m = m0 + ty * 8 + i;
        #pragma unroll
        for (int j = 0; j < 8; j++) {
            int n = n0 + tx * 8 + j;
            if (n < Nn) {
                float v = acc[i][j];
                if (epi) {
                    float gb = __fmul_rn(gs[n], BNS);
                    v = __fadd_rn(__fmul_rn(v, gb), bs[n]);
                    v = v > 0.f ? v : __fmul_rn(0.2f, v);
                }
                Cc[(size_t)m * ldc + n] = v;
            }
        }
    }
}

// ---------------- BN + LReLU + max over k (on edge conv outputs) ----------------
__global__ __launch_bounds__(256) void aggregate_kernel(
    const float* __restrict__ ye,   // [NROWS*KNN, O]
    int O,
    const float* __restrict__ gsc, const float* __restrict__ bia,
    float* __restrict__ outc) {     // xc + colOut, ld 960

    int row = blockIdx.x;
    int t = threadIdx.x;
    const float* yrow = ye + (size_t)row * KNN * O;

    for (int o = t; o < O; o += 256) {
        float gb = __fmul_rn(gsc[o], BNS);
        float bo = bia[o];
        float mx = -FLT_MAX;
        #pragma unroll
        for (int k = 0; k < KNN; k++) {
            float v = yrow[(size_t)k * O + o];
            v = __fadd_rn(__fmul_rn(v, gb), bo);
            v = v > 0.f ? v : __fmul_rn(0.2f, v);
            mx = fmaxf(mx, v);
        }
        outc[(size_t)row * 960 + o] = mx;
    }
}

// ---------------- global max-pool over N ----------------
__global__ void rowmax_kernel(const float* __restrict__ y, float* __restrict__ feat) {
    int b = blockIdx.x;
    int o = threadIdx.x;  // 512 threads
    float mx = -FLT_MAX;
    const float* base = y + (size_t)b * NPTS * 512 + o;
    for (int n = 0; n < NPTS; n++) mx = fmaxf(mx, base[(size_t)n * 512]);
    feat[b * 512 + o] = mx;
}

// ---------------- final linear: out[b,j] = sum_o feat[b,o]*We[j,o] ----------------
__global__ __launch_bounds__(256) void final_kernel(const float* __restrict__ We,
                                                    const float* __restrict__ feat,
                                                    float* __restrict__ out) {
    __shared__ float sf[BATCH * 512];
    int t = threadIdx.x;
    for (int i = t; i < BATCH * 512; i += 256) sf[i] = feat[i];
    __syncthreads();
    int j = t;  // 256 outputs
    float acc[BATCH] = {0.f, 0.f, 0.f, 0.f};
    for (int o = 0; o < 512; o++) {        // ascending, single accumulator
        float w = We[(size_t)j * 512 + o];
        #pragma unroll
        for (int b = 0; b < BATCH; b++) acc[b] = fmaf(sf[b * 512 + o], w, acc[b]);
    }
    #pragma unroll
    for (int b = 0; b < BATCH; b++) out[b * 256 + j] = acc[b];
}

// ---------------- host side ----------------
static void* sym_addr(const void* sym) { void* p; cudaGetSymbolAddress(&p, sym); return p; }

extern "C" void kernel_launch(void* const* d_in, const int* in_sizes, int n_in,
                              void* d_out, int out_size) {
    (void)in_sizes; (void)n_in; (void)out_size;
    const float* x = (const float*)d_in[0];
    const float* Wl[5] = { (const float*)d_in[1], (const float*)d_in[4],
                           (const float*)d_in[7], (const float*)d_in[10],
                           (const float*)d_in[13] };
    const float* gl[5] = { (const float*)d_in[2], (const float*)d_in[5],
                           (const float*)d_in[8], (const float*)d_in[11],
                           (const float*)d_in[14] };
    const float* bl[5] = { (const float*)d_in[3], (const float*)d_in[6],
                           (const float*)d_in[9], (const float*)d_in[12],
                           (const float*)d_in[15] };
    const float* We = (const float*)d_in[16];
    float* out = (float*)d_out;

    float* xc   = (float*)sym_addr(g_xc);
    float* ye   = (float*)sym_addr(g_ye);
    float* q    = (float*)sym_addr(g_q);
    float* sq   = (float*)sym_addr(g_sq);
    int*   idxp = (int*)sym_addr(g_idx);
    float* feat = (float*)sym_addr(g_feat);

    struct Layer { int C, O, colIn, colOut; };
    Layer L[4] = {
        {3,   64,  -1,  0},
        {64,  128,  0,  64},
        {128, 256, 64,  192},
        {256, 512, 192, 448},
    };

    for (int li = 0; li < 4; li++) {
        const float* X = (li == 0) ? x : (xc + L[li].colIn);
        int ld = (li == 0) ? 3 : 960;
        int C = L[li].C, O = L[li].O;

        if (C >= 64) {
            // XLA GPU row-reduce shape: warp/row, stride-32 lanes, shfl tree
            sqnorm_warp_kernel<<<(NROWS * 32 + 255) / 256, 256>>>(X, ld, C, sq);
        } else {
            sqnorm_kernel<<<(NROWS + 255) / 256, 256>>>(X, ld, C, sq);
        }
        knn_kernel<<<NROWS, 256>>>(X, ld, C, sq, idxp);

        // edge conv: ye[edge, o] = sum_{c=0}^{2C-1} e[edge,c] * W[o,c], ascending c
        {
            dim3 grid((O + BN_ - 1) / BN_, (NROWS * KNN) / BM);
            sgemm_kernel<<<grid, 256>>>(X, ld, Wl[li], 2 * C,
                                        ye, O, O, 2 * C, C,
                                        1, idxp, 0, nullptr, nullptr);
        }
        aggregate_kernel<<<NROWS, 256>>>(ye, O, gl[li], bl[li],
                                         xc + L[li].colOut);
    }

    // conv5: y = LReLU(BN(xc @ W5^T)) into q (ld=512)
    {
        dim3 grid(512 / BN_, NROWS / BM);
        sgemm_kernel<<<grid, 256>>>(xc, 960, Wl[4], 960,
                                    q, 512, 512, 960, 0,
                                    0, nullptr, 1, gl[4], bl[4]);
    }
    rowmax_kernel<<<BATCH, 512>>>(q, feat);
    final_kernel<<<1, 256>>>(We, feat, out);
}

// round 12
// speedup vs baseline: 1.0553x; 1.0553x over previous
#include <cuda_runtime.h>
#include <cfloat>
#include <cstddef>

#define BATCH 4
#define NPTS  1024
#define NROWS (BATCH*NPTS)
#define KNN   20
#define BNS   0.99999500003749968f   // 1/sqrt(1+1e-5)

// ---------------- scratch (static device globals; no allocation) ----------------
__device__ float g_xc[NROWS * 960];              // concat feature buffer [x1|x2|x3|x4]
__device__ float g_ye[NROWS * KNN * 512];        // per-edge conv output (ld = O)
__device__ float g_q[NROWS * 512];               // conv5 out
__device__ float g_sq[NROWS];                    // squared norms
__device__ int   g_idx[NROWS * KNN];             // knn indices (within-batch)
__device__ float g_feat[BATCH * 512];            // global max-pooled features

// ---------------- squared norms, small C: strict sequential (DO NOT CHANGE) -------
__global__ void sqnorm_kernel(const float* __restrict__ X, int ld, int C,
                              float* __restrict__ sq) {
    int i = blockIdx.x * blockDim.x + threadIdx.x;
    if (i >= NROWS) return;
    const float* r = X + (size_t)i * ld;
    float s = 0.f;
    for (int c = 0; c < C; c++) {
        float p = __fmul_rn(r[c], r[c]);
        s = __fadd_rn(s, p);
    }
    sq[i] = s;
}

// ---------------- squared norms, C>=64: XLA warp row-reduce (DO NOT CHANGE) -------
__global__ void sqnorm_warp_kernel(const float* __restrict__ X, int ld, int C,
                                   float* __restrict__ sq) {
    int gt = blockIdx.x * blockDim.x + threadIdx.x;
    int warp = gt >> 5;
    int lane = gt & 31;
    if (warp >= NROWS) return;
    const float* r = X + (size_t)warp * ld;
    float s = 0.f;
    for (int c = lane; c < C; c += 32) s = fmaf(r[c], r[c], s);
    #pragma unroll
    for (int off = 16; off > 0; off >>= 1)
        s = __fadd_rn(s, __shfl_down_sync(0xffffffffu, s, off));
    if (lane == 0) sq[warp] = s;
}

// ---------------- knn: distance arithmetic identical to passing R9 ---------------
// Selection: per-thread cached argmax + shfl trees (same compare semantics).
__global__ __launch_bounds__(256) void knn_kernel(const float* __restrict__ X,
                                                  int ld, int C,
                                                  const float* __restrict__ sq,
                                                  int* __restrict__ idx) {
    int row = blockIdx.x;               // b*1024 + n
    int b = row >> 10;
    int n = row & 1023;
    const float* base = X + (size_t)b * NPTS * ld;

    __shared__ __align__(16) float ctr[256];
    __shared__ float d[NPTS];
    __shared__ float wv_s[8];
    __shared__ int   wi_s[8];
    __shared__ int   win_s;

    int t = threadIdx.x;
    int lane = t & 31, warp = t >> 5;
    for (int c = t; c < C; c += 256) ctr[c] = base[(size_t)n * ld + c];
    __syncthreads();

    float sqn = sq[row];

    if ((C & 3) == 0 && (ld & 3) == 0) {
        int C4 = C >> 2;
        for (int m = t; m < NPTS; m += 256) {
            const float4* xm = (const float4*)(base + (size_t)m * ld);
            const float4* cc = (const float4*)ctr;
            float s = 0.f;
            #pragma unroll 4
            for (int c = 0; c < C4; c++) {
                float4 v = xm[c], u = cc[c];
                s = fmaf(v.x, u.x, s);
                s = fmaf(v.y, u.y, s);
                s = fmaf(v.z, u.z, s);
                s = fmaf(v.w, u.w, s);
            }
            float dd = __fmul_rn(2.0f, s);
            dd = __fsub_rn(dd, sqn);
            dd = __fsub_rn(dd, sq[(b << 10) + m]);
            d[m] = dd;
        }
    } else {
        for (int m = t; m < NPTS; m += 256) {
            const float* xm = base + (size_t)m * ld;
            float s = 0.f;
            for (int c = 0; c < C; c++) {
                float p = __fmul_rn(xm[c], ctr[c]);
                s = __fadd_rn(s, p);
            }
            float dd = __fmul_rn(2.0f, s);
            dd = __fsub_rn(dd, sqn);
            dd = __fsub_rn(dd, sq[(b << 10) + m]);
            d[m] = dd;
        }
    }
    __syncthreads();

    // per-thread local argmax over its 4 strided elements (value desc, index asc)
    float bv = -FLT_MAX; int bi = NPTS;
    #pragma unroll
    for (int u = 0; u < 4; u++) {
        int m = t + u * 256;
        float v = d[m];
        if (v > bv || (v == bv && m < bi)) { bv = v; bi = m; }
    }

    for (int r = 0; r < KNN; r++) {
        float rv2 = bv; int ri2 = bi;
        #pragma unroll
        for (int off = 16; off > 0; off >>= 1) {
            float ov = __shfl_down_sync(0xffffffffu, rv2, off);
            int   oi = __shfl_down_sync(0xffffffffu, ri2, off);
            if (ov > rv2 || (ov == rv2 && oi < ri2)) { rv2 = ov; ri2 = oi; }
        }
        if (lane == 0) { wv_s[warp] = rv2; wi_s[warp] = ri2; }
        __syncthreads();
        if (warp == 0) {
            float fv = (lane < 8) ? wv_s[lane] : -FLT_MAX;
            int   fi = (lane < 8) ? wi_s[lane] : NPTS;
            #pragma unroll
            for (int off = 4; off > 0; off >>= 1) {
                float ov = __shfl_down_sync(0xffffffffu, fv, off);
                int   oi = __shfl_down_sync(0xffffffffu, fi, off);
                if (ov > fv || (ov == fv && oi < fi)) { fv = ov; fi = oi; }
            }
            if (lane == 0) {
                win_s = fi;
                idx[row * KNN + r] = fi;
            }
        }
        __syncthreads();
        int w = win_s;
        if ((w & 255) == t) {            // owner invalidates + rescans its 4 elems
            d[w] = -FLT_MAX;
            bv = -FLT_MAX; bi = NPTS;
            #pragma unroll
            for (int u = 0; u < 4; u++) {
                int m = t + u * 256;
                float v = d[m];
                if (v > bv || (v == bv && m < bi)) { bv = v; bi = m; }
            }
        }
    }
}

// ---------------- fp32 SGEMM, ascending-k single accumulator ---------------------
// NUMERICS IDENTICAL TO R9 (literal edge einsum). Software-pipelined global loads.
// mode 0: a[m,k] = A[m*lda + k]
// mode 1: m = edge id; k <  Chalf: a = fl(A[nbr,k] - A[ctr,k])
//                      k >= Chalf: a = A[ctr, k-Chalf]
#define BM 128
#define BN_ 128
#define BK 16

__global__ __launch_bounds__(256) void sgemm_kernel(
    const float* __restrict__ A, int lda,
    const float* __restrict__ Bw, int ldb,
    float* __restrict__ Cc, int ldc,
    int Nn, int Kk, int Chalf,
    int mode, const int* __restrict__ idx,
    int epi, const float* __restrict__ gs, const float* __restrict__ bs) {

    __shared__ __align__(16) float As[BK][BM + 4];
    __shared__ __align__(16) float Bs[BK][BN_ + 4];
    __shared__ int nbr_s[BM];
    __shared__ int ctr_s[BM];

    int t  = threadIdx.x;
    int tx = t & 15, ty = t >> 4;
    int m0 = blockIdx.y * BM;
    int n0 = blockIdx.x * BN_;

    if (mode == 1) {
        if (t < BM) {
            int edge = m0 + t;
            int row = edge / KNN;          // global point row 0..4095
            int b = row >> 10;
            nbr_s[t] = (b << 10) + idx[edge];
            ctr_s[t] = row;
        }
        __syncthreads();
    }

    float acc[8][8];
    #pragma unroll
    for (int i = 0; i < 8; i++)
        #pragma unroll
        for (int j = 0; j < 8; j++) acc[i][j] = 0.f;

    int kTiles = (Kk + BK - 1) / BK;

    // ---- load tile 0 into smem ----
    #pragma unroll
    for (int u = 0; u < 8; u++) {
        int e = t + u * 256;
        int i = e >> 4, k = e & 15;
        int gk = k;
        float v = 0.f;
        if (gk < Kk) {
            if (mode == 1) {
                if (gk < Chalf)
                    v = __fsub_rn(A[(size_t)nbr_s[i] * lda + gk],
                                  A[(size_t)ctr_s[i] * lda + gk]);
                else
                    v = A[(size_t)ctr_s[i] * lda + (gk - Chalf)];
            } else {
                v = A[(size_t)(m0 + i) * lda + gk];
            }
        }
        As[k][i] = v;
    }
    #pragma unroll
    for (int u = 0; u < 8; u++) {
        int e = t + u * 256;
        int j = e >> 4, k = e & 15;
        int gk = k;
        float v = 0.f;
        if (gk < Kk && (n0 + j) < Nn)
            v = Bw[(size_t)(n0 + j) * ldb + gk];
        Bs[k][j] = v;
    }
    __syncthreads();

    for (int kt = 0; kt < kTiles; kt++) {
        // ---- prefetch next tile into registers (overlaps with FFMA block) ----
        float pa[8], pb[8];
        bool more = (kt + 1 < kTiles);
        if (more) {
            int k0n = (kt + 1) * BK;
            #pragma unroll
            for (int u = 0; u < 8; u++) {
                int e = t + u * 256;
                int i = e >> 4, k = e & 15;
                int gk = k0n + k;
                float v = 0.f;
                if (gk < Kk) {
                    if (mode == 1) {
                        if (gk < Chalf)
                            v = __fsub_rn(A[(size_t)nbr_s[i] * lda + gk],
                                          A[(size_t)ctr_s[i] * lda + gk]);
                        else
                            v = A[(size_t)ctr_s[i] * lda + (gk - Chalf)];
                    } else {
                        v = A[(size_t)(m0 + i) * lda + gk];
                    }
                }
                pa[u] = v;
            }
            #pragma unroll
            for (int u = 0; u < 8; u++) {
                int e = t + u * 256;
                int j = e >> 4, k = e & 15;
                int gk = k0n + k;
                float v = 0.f;
                if (gk < Kk && (n0 + j) < Nn)
                    v = Bw[(size_t)(n0 + j) * ldb + gk];
                pb[u] = v;
            }
        }

        // ---- compute current tile (ascending k -> preserves accumulation order) ----
        #pragma unroll
        for (int k = 0; k < BK; k++) {
            float a[8], b[8];
            *(float4*)&a[0] = *(const float4*)&As[k][ty * 8];
            *(float4*)&a[4] = *(const float4*)&As[k][ty * 8 + 4];
            *(float4*)&b[0] = *(const float4*)&Bs[k][tx * 8];
            *(float4*)&b[4] = *(const float4*)&Bs[k][tx * 8 + 4];
            #pragma unroll
            for (int i = 0; i < 8; i++)
                #pragma unroll
                for (int j = 0; j < 8; j++)
                    acc[i][j] = fmaf(a[i], b[j], acc[i][j]);
        }
        __syncthreads();

        if (more) {
            #pragma unroll
            for (int u = 0; u < 8; u++) {
                int e = t + u * 256;
                int i = e >> 4, k = e & 15;
                As[k][i] = pa[u];
            }
            #pragma unroll
            for (int u = 0; u < 8; u++) {
                int e = t + u * 256;
                int j = e >> 4, k = e & 15;
                Bs[k][j] = pb[u];
            }
            __syncthreads();
        }
    }

    #pragma unroll
    for (int i = 0; i < 8; i++) {
        int m = m0 + ty * 8 + i;
        #pragma unroll
        for (int j = 0; j < 8; j++) {
            int n = n0 + tx * 8 + j;
            if (n < Nn) {
                float v = acc[i][j];
                if (epi) {
                    float gb = __fmul_rn(gs[n], BNS);
                    v = __fadd_rn(__fmul_rn(v, gb), bs[n]);
                    v = v > 0.f ? v : __fmul_rn(0.2f, v);
                }
                Cc[(size_t)m * ldc + n] = v;
            }
        }
    }
}

// ---------------- BN + LReLU + max over k (on edge conv outputs) ----------------
__global__ __launch_bounds__(256) void aggregate_kernel(
    const float* __restrict__ ye,   // [NROWS*KNN, O]
    int O,
    const float* __restrict__ gsc, const float* __restrict__ bia,
    float* __restrict__ outc) {     // xc + colOut, ld 960

    int row = blockIdx.x;
    int t = threadIdx.x;
    const float* yrow = ye + (size_t)row * KNN * O;

    for (int o = t; o < O; o += 256) {
        float gb = __fmul_rn(gsc[o], BNS);
        float bo = bia[o];
        float mx = -FLT_MAX;
        #pragma unroll
        for (int k = 0; k < KNN; k++) {
            float v = yrow[(size_t)k * O + o];
            v = __fadd_rn(__fmul_rn(v, gb), bo);
            v = v > 0.f ? v : __fmul_rn(0.2f, v);
            mx = fmaxf(mx, v);
        }
        outc[(size_t)row * 960 + o] = mx;
    }
}

// ---------------- global max-pool over N ----------------
__global__ void rowmax_kernel(const float* __restrict__ y, float* __restrict__ feat) {
    int b = blockIdx.x;
    int o = threadIdx.x;  // 512 threads
    float mx = -FLT_MAX;
    const float* base = y + (size_t)b * NPTS * 512 + o;
    for (int n = 0; n < NPTS; n++) mx = fmaxf(mx, base[(size_t)n * 512]);
    feat[b * 512 + o] = mx;
}

// ---------------- final linear: out[b,j] = sum_o feat[b,o]*We[j,o] ----------------
__global__ __launch_bounds__(256) void final_kernel(const float* __restrict__ We,
                                                    const float* __restrict__ feat,
                                                    float* __restrict__ out) {
    __shared__ float sf[BATCH * 512];
    int t = threadIdx.x;
    for (int i = t; i < BATCH * 512; i += 256) sf[i] = feat[i];
    __syncthreads();
    int j = t;  // 256 outputs
    float acc[BATCH] = {0.f, 0.f, 0.f, 0.f};
    for (int o = 0; o < 512; o++) {        // ascending, single accumulator
        float w = We[(size_t)j * 512 + o];
        #pragma unroll
        for (int b = 0; b < BATCH; b++) acc[b] = fmaf(sf[b * 512 + o], w, acc[b]);
    }
    #pragma unroll
    for (int b = 0; b < BATCH; b++) out[b * 256 + j] = acc[b];
}

// ---------------- host side ----------------
static void* sym_addr(const void* sym) { void* p; cudaGetSymbolAddress(&p, sym); return p; }

extern "C" void kernel_launch(void* const* d_in, const int* in_sizes, int n_in,
                              void* d_out, int out_size) {
    (void)in_sizes; (void)n_in; (void)out_size;
    const float* x = (const float*)d_in[0];
    const float* Wl[5] = { (const float*)d_in[1], (const float*)d_in[4],
                           (const float*)d_in[7], (const float*)d_in[10],
                           (const float*)d_in[13] };
    const float* gl[5] = { (const float*)d_in[2], (const float*)d_in[5],
                           (const float*)d_in[8], (const float*)d_in[11],
                           (const float*)d_in[14] };
    const float* bl[5] = { (const float*)d_in[3], (const float*)d_in[6],
                           (const float*)d_in[9], (const float*)d_in[12],
                           (const float*)d_in[15] };
    const float* We = (const float*)d_in[16];
    float* out = (float*)d_out;

    float* xc   = (float*)sym_addr(g_xc);
    float* ye   = (float*)sym_addr(g_ye);
    float* q    = (float*)sym_addr(g_q);
    float* sq   = (float*)sym_addr(g_sq);
    int*   idxp = (int*)sym_addr(g_idx);
    float* feat = (float*)sym_addr(g_feat);

    struct Layer { int C, O, colIn, colOut; };
    Layer L[4] = {
        {3,   64,  -1,  0},
        {64,  128,  0,  64},
        {128, 256, 64,  192},
        {256, 512, 192, 448},
    };

    for (int li = 0; li < 4; li++) {
        const float* X = (li == 0) ? x : (xc + L[li].colIn);
        int ld = (li == 0) ? 3 : 960;
        int C = L[li].C, O = L[li].O;

        if (C >= 64) {
            sqnorm_warp_kernel<<<(NROWS * 32 + 255) / 256, 256>>>(X, ld, C, sq);
        } else {
            sqnorm_kernel<<<(NROWS + 255) / 256, 256>>>(X, ld, C, sq);
        }
        knn_kernel<<<NROWS, 256>>>(X, ld, C, sq, idxp);

        // edge conv (literal): ye[edge, o] = sum_{c=0}^{2C-1} e[edge,c]*W[o,c]
        {
            dim3 grid((O + BN_ - 1) / BN_, (NROWS * KNN) / BM);
            sgemm_kernel<<<grid, 256>>>(X, ld, Wl[li], 2 * C,
                                        ye, O, O, 2 * C, C,
                                        1, idxp, 0, nullptr, nullptr);
        }
        aggregate_kernel<<<NROWS, 256>>>(ye, O, gl[li], bl[li],
                                         xc + L[li].colOut);
    }

    // conv5: y = LReLU(BN(xc @ W5^T)) into q (ld=512)
    {
        dim3 grid(512 / BN_, NROWS / BM);
        sgemm_kernel<<<grid, 256>>>(xc, 960, Wl[4], 960,
                                    q, 512, 512, 960, 0,
                                    0, nullptr, 1, gl[4], bl[4]);
    }
    rowmax_kernel<<<BATCH, 512>>>(q, feat);
    final_kernel<<<1, 256>>>(We, feat, out);
}

// round 13
// speedup vs baseline: 1.2180x; 1.1542x over previous
#include <cuda_runtime.h>
#include <cfloat>
#include <cstddef>

#define BATCH 4
#define NPTS  1024
#define NROWS (BATCH*NPTS)
#define KNN   20
#define BNS   0.99999500003749968f   // 1/sqrt(1+1e-5)

// ---------------- scratch (static device globals; no allocation) ----------------
__device__ float g_xc[NROWS * 960];              // concat feature buffer [x1|x2|x3|x4]
__device__ float g_ye[NROWS * KNN * 512];        // per-edge conv output (ld = O)
__device__ float g_q[NROWS * 512];               // conv5 out
__device__ float g_sq[NROWS];                    // squared norms
__device__ int   g_idx[NROWS * KNN];             // knn indices (within-batch)
__device__ float g_feat[BATCH * 512];            // global max-pooled features

// ---------------- packed f32x2 FMA (two independent IEEE fp32 FMAs) --------------
__device__ __forceinline__ void ffma2(unsigned long long& d,
                                      unsigned long long a,
                                      unsigned long long b) {
    asm("fma.rn.f32x2 %0, %1, %2, %3;" : "=l"(d) : "l"(a), "l"(b), "l"(d));
}
__device__ __forceinline__ unsigned long long bcast2(float x) {
    unsigned long long r;
    unsigned xb = __float_as_uint(x);
    asm("mov.b64 %0, {%1, %1};" : "=l"(r) : "r"(xb));
    return r;
}

// ---------------- squared norms, small C: strict sequential (DO NOT CHANGE) -------
__global__ void sqnorm_kernel(const float* __restrict__ X, int ld, int C,
                              float* __restrict__ sq) {
    int i = blockIdx.x * blockDim.x + threadIdx.x;
    if (i >= NROWS) return;
    const float* r = X + (size_t)i * ld;
    float s = 0.f;
    for (int c = 0; c < C; c++) {
        float p = __fmul_rn(r[c], r[c]);
        s = __fadd_rn(s, p);
    }
    sq[i] = s;
}

// ---------------- squared norms, C>=64: XLA warp row-reduce (DO NOT CHANGE) -------
__global__ void sqnorm_warp_kernel(const float* __restrict__ X, int ld, int C,
                                   float* __restrict__ sq) {
    int gt = blockIdx.x * blockDim.x + threadIdx.x;
    int warp = gt >> 5;
    int lane = gt & 31;
    if (warp >= NROWS) return;
    const float* r = X + (size_t)warp * ld;
    float s = 0.f;
    for (int c = lane; c < C; c += 32) s = fmaf(r[c], r[c], s);
    #pragma unroll
    for (int off = 16; off > 0; off >>= 1)
        s = __fadd_rn(s, __shfl_down_sync(0xffffffffu, s, off));
    if (lane == 0) sq[warp] = s;
}

// ---------------- knn: 4 rows per block; per-row arithmetic identical to R9 -------
__global__ __launch_bounds__(256) void knn_kernel(const float* __restrict__ X,
                                                  int ld, int C,
                                                  const float* __restrict__ sq,
                                                  int* __restrict__ idx) {
    int row0 = blockIdx.x * 4;            // 4 consecutive rows, same batch
    int b = row0 >> 10;
    int n0r = row0 & 1023;
    const float* base = X + (size_t)b * NPTS * ld;

    __shared__ __align__(16) float ctr4[4][256];
    __shared__ float d4[4][NPTS];
    __shared__ float wv_s[8];
    __shared__ int   wi_s[8];
    __shared__ int   win_s;

    int t = threadIdx.x;
    int lane = t & 31, warp = t >> 5;

    for (int rc = t; rc < 4 * C; rc += 256) {
        int r = rc / C, c = rc - r * C;
        ctr4[r][c] = base[(size_t)(n0r + r) * ld + c];
    }
    __syncthreads();

    float sqn[4];
    #pragma unroll
    for (int r = 0; r < 4; r++) sqn[r] = sq[row0 + r];

    if ((C & 3) == 0 && (ld & 3) == 0) {
        int C4 = C >> 2;
        const float4* xm[4];
        #pragma unroll
        for (int u = 0; u < 4; u++)
            xm[u] = (const float4*)(base + (size_t)(t + u * 256) * ld);

        float s[4][4];                    // [cand u][row r]
        #pragma unroll
        for (int u = 0; u < 4; u++)
            #pragma unroll
            for (int r = 0; r < 4; r++) s[u][r] = 0.f;

        for (int c = 0; c < C4; c++) {
            float4 v[4], uu[4];
            #pragma unroll
            for (int u = 0; u < 4; u++) v[u] = xm[u][c];
            #pragma unroll
            for (int r = 0; r < 4; r++) uu[r] = ((const float4*)ctr4[r])[c];
            #pragma unroll
            for (int u = 0; u < 4; u++)
                #pragma unroll
                for (int r = 0; r < 4; r++) {
                    // identical per-(cand,row) FMA order to the passing kernel
                    s[u][r] = fmaf(v[u].x, uu[r].x, s[u][r]);
                    s[u][r] = fmaf(v[u].y, uu[r].y, s[u][r]);
                    s[u][r] = fmaf(v[u].z, uu[r].z, s[u][r]);
                    s[u][r] = fmaf(v[u].w, uu[r].w, s[u][r]);
                }
        }
        #pragma unroll
        for (int u = 0; u < 4; u++) {
            int m = t + u * 256;
            float sqm = sq[(b << 10) + m];
            #pragma unroll
            for (int r = 0; r < 4; r++) {
                float dd = __fmul_rn(2.0f, s[u][r]);
                dd = __fsub_rn(dd, sqn[r]);
                dd = __fsub_rn(dd, sqm);
                d4[r][m] = dd;
            }
        }
    } else {
        for (int u = 0; u < 4; u++) {
            int m = t + u * 256;
            const float* xmp = base + (size_t)m * ld;
            float sqm = sq[(b << 10) + m];
            for (int r = 0; r < 4; r++) {
                float s = 0.f;
                for (int c = 0; c < C; c++) {
                    float p = __fmul_rn(xmp[c], ctr4[r][c]);
                    s = __fadd_rn(s, p);
                }
                float dd = __fmul_rn(2.0f, s);
                dd = __fsub_rn(dd, sqn[r]);
                dd = __fsub_rn(dd, sqm);
                d4[r][m] = dd;
            }
        }
    }
    __syncthreads();

    // selection per row, same semantics as the passing kernel
    for (int r = 0; r < 4; r++) {
        float* d = d4[r];
        int row = row0 + r;

        float bv = -FLT_MAX; int bi = NPTS;
        #pragma unroll
        for (int u = 0; u < 4; u++) {
            int m = t + u * 256;
            float v = d[m];
            if (v > bv || (v == bv && m < bi)) { bv = v; bi = m; }
        }

        for (int rr = 0; rr < KNN; rr++) {
            float rv2 = bv; int ri2 = bi;
            #pragma unroll
            for (int off = 16; off > 0; off >>= 1) {
                float ov = __shfl_down_sync(0xffffffffu, rv2, off);
                int   oi = __shfl_down_sync(0xffffffffu, ri2, off);
                if (ov > rv2 || (ov == rv2 && oi < ri2)) { rv2 = ov; ri2 = oi; }
            }
            if (lane == 0) { wv_s[warp] = rv2; wi_s[warp] = ri2; }
            __syncthreads();
            if (warp == 0) {
                float fv = (lane < 8) ? wv_s[lane] : -FLT_MAX;
                int   fi = (lane < 8) ? wi_s[lane] : NPTS;
                #pragma unroll
                for (int off = 4; off > 0; off >>= 1) {
                    float ov = __shfl_down_sync(0xffffffffu, fv, off);
                    int   oi = __shfl_down_sync(0xffffffffu, fi, off);
                    if (ov > fv || (ov == fv && oi < fi)) { fv = ov; fi = oi; }
                }
                if (lane == 0) {
                    win_s = fi;
                    idx[row * KNN + rr] = fi;
                }
            }
            __syncthreads();
            int w = win_s;
            if ((w & 255) == t) {
                d[w] = -FLT_MAX;
                bv = -FLT_MAX; bi = NPTS;
                #pragma unroll
                for (int u = 0; u < 4; u++) {
                    int m = t + u * 256;
                    float v = d[m];
                    if (v > bv || (v == bv && m < bi)) { bv = v; bi = m; }
                }
            }
        }
        __syncthreads();
    }
}

// ---------------- fp32 SGEMM via packed f32x2 FMA --------------------------------
// Per-output accumulation: single chain, ascending k — bitwise identical to fmaf.
// mode 0: a[m,k] = A[m*lda + k]
// mode 1: m = edge id; k <  Chalf: a = fl(A[nbr,k] - A[ctr,k])
//                      k >= Chalf: a = A[ctr, k-Chalf]
#define BM 128
#define BN_ 128
#define BK 16

__global__ __launch_bounds__(256) void sgemm_kernel(
    const float* __restrict__ A, int lda,
    const float* __restrict__ Bw, int ldb,
    float* __restrict__ Cc, int ldc,
    int Nn, int Kk, int Chalf,
    int mode, const int* __restrict__ idx,
    int epi, const float* __restrict__ gs, const float* __restrict__ bs) {

    __shared__ __align__(16) float As[BK][BM + 4];
    __shared__ __align__(16) float Bs[BK][BN_ + 4];
    __shared__ int nbr_s[BM];
    __shared__ int ctr_s[BM];

    int t  = threadIdx.x;
    int tx = t & 15, ty = t >> 4;
    int m0 = blockIdx.y * BM;
    int n0 = blockIdx.x * BN_;

    if (mode == 1) {
        if (t < BM) {
            int edge = m0 + t;
            int row = edge / KNN;          // global point row 0..4095
            int b = row >> 10;
            nbr_s[t] = (b << 10) + idx[edge];
            ctr_s[t] = row;
        }
        __syncthreads();
    }

    unsigned long long acc2[8][4];        // [i][j-pair]; lanes = two fp32 chains
    #pragma unroll
    for (int i = 0; i < 8; i++)
        #pragma unroll
        for (int j = 0; j < 4; j++) acc2[i][j] = 0ull;

    int kTiles = (Kk + BK - 1) / BK;

    // ---- load tile 0 ----
    #pragma unroll
    for (int u = 0; u < 8; u++) {
        int e = t + u * 256;
        int i = e >> 4, k = e & 15;
        float v = 0.f;
        if (k < Kk) {
            if (mode == 1) {
                if (k < Chalf)
                    v = __fsub_rn(A[(size_t)nbr_s[i] * lda + k],
                                  A[(size_t)ctr_s[i] * lda + k]);
                else
                    v = A[(size_t)ctr_s[i] * lda + (k - Chalf)];
            } else {
                v = A[(size_t)(m0 + i) * lda + k];
            }
        }
        As[k][i] = v;
    }
    #pragma unroll
    for (int u = 0; u < 8; u++) {
        int e = t + u * 256;
        int j = e >> 4, k = e & 15;
        float v = 0.f;
        if (k < Kk && (n0 + j) < Nn)
            v = Bw[(size_t)(n0 + j) * ldb + k];
        Bs[k][j] = v;
    }
    __syncthreads();

    for (int kt = 0; kt < kTiles; kt++) {
        float pa[8], pb[8];
        bool more = (kt + 1 < kTiles);
        if (more) {
            int k0n = (kt + 1) * BK;
            #pragma unroll
            for (int u = 0; u < 8; u++) {
                int e = t + u * 256;
                int i = e >> 4, k = e & 15;
                int gk = k0n + k;
                float v = 0.f;
                if (gk < Kk) {
                    if (mode == 1) {
                        if (gk < Chalf)
                            v = __fsub_rn(A[(size_t)nbr_s[i] * lda + gk],
                                          A[(size_t)ctr_s[i] * lda + gk]);
                        else
                            v = A[(size_t)ctr_s[i] * lda + (gk - Chalf)];
                    } else {
                        v = A[(size_t)(m0 + i) * lda + gk];
                    }
                }
                pa[u] = v;
            }
            #pragma unroll
            for (int u = 0; u < 8; u++) {
                int e = t + u * 256;
                int j = e >> 4, k = e & 15;
                int gk = k0n + k;
                float v = 0.f;
                if (gk < Kk && (n0 + j) < Nn)
                    v = Bw[(size_t)(n0 + j) * ldb + gk];
                pb[u] = v;
            }
        }

        // ---- compute current tile (ascending k) ----
        #pragma unroll
        for (int k = 0; k < BK; k++) {
            float a[8];
            *(float4*)&a[0] = *(const float4*)&As[k][ty * 8];
            *(float4*)&a[4] = *(const float4*)&As[k][ty * 8 + 4];
            ulonglong2 bb0 = *(const ulonglong2*)&Bs[k][tx * 8];
            ulonglong2 bb1 = *(const ulonglong2*)&Bs[k][tx * 8 + 4];
            unsigned long long b2[4] = { bb0.x, bb0.y, bb1.x, bb1.y };
            #pragma unroll
            for (int i = 0; i < 8; i++) {
                unsigned long long aa = bcast2(a[i]);
                #pragma unroll
                for (int j = 0; j < 4; j++) ffma2(acc2[i][j], aa, b2[j]);
            }
        }
        __syncthreads();

        if (more) {
            #pragma unroll
            for (int u = 0; u < 8; u++) {
                int e = t + u * 256;
                int i = e >> 4, k = e & 15;
                As[k][i] = pa[u];
            }
            #pragma unroll
            for (int u = 0; u < 8; u++) {
                int e = t + u * 256;
                int j = e >> 4, k = e & 15;
                Bs[k][j] = pb[u];
            }
            __syncthreads();
        }
    }

    #pragma unroll
    for (int i = 0; i < 8; i++) {
        int m = m0 + ty * 8 + i;
        #pragma unroll
        for (int j2 = 0; j2 < 4; j2++) {
            unsigned long long p = acc2[i][j2];
            float lo = __uint_as_float((unsigned)(p & 0xffffffffull));
            float hi = __uint_as_float((unsigned)(p >> 32));
            #pragma unroll
            for (int h = 0; h < 2; h++) {
                int n = n0 + tx * 8 + 2 * j2 + h;
                if (n < Nn) {
                    float v = h ? hi : lo;
                    if (epi) {
                        float gb = __fmul_rn(gs[n], BNS);
                        v = __fadd_rn(__fmul_rn(v, gb), bs[n]);
                        v = v > 0.f ? v : __fmul_rn(0.2f, v);
                    }
                    Cc[(size_t)m * ldc + n] = v;
                }
            }
        }
    }
}

// ---------------- BN + LReLU + max over k (on edge conv outputs) ----------------
__global__ __launch_bounds__(256) void aggregate_kernel(
    const float* __restrict__ ye,   // [NROWS*KNN, O]
    int O,
    const float* __restrict__ gsc, const float* __restrict__ bia,
    float* __restrict__ outc) {     // xc + colOut, ld 960

    int row = blockIdx.x;
    int t = threadIdx.x;
    const float* yrow = ye + (size_t)row * KNN * O;

    for (int o = t; o < O; o += 256) {
        float gb = __fmul_rn(gsc[o], BNS);
        float bo = bia[o];
        float mx = -FLT_MAX;
        #pragma unroll
        for (int k = 0; k < KNN; k++) {
            float v = yrow[(size_t)k * O + o];
            v = __fadd_rn(__fmul_rn(v, gb), bo);
            v = v > 0.f ? v : __fmul_rn(0.2f, v);
            mx = fmaxf(mx, v);
        }
        outc[(size_t)row * 960 + o] = mx;
    }
}

// ---------------- global max-pool over N ----------------
__global__ void rowmax_kernel(const float* __restrict__ y, float* __restrict__ feat) {
    int b = blockIdx.x;
    int o = threadIdx.x;  // 512 threads
    float mx = -FLT_MAX;
    const float* base = y + (size_t)b * NPTS * 512 + o;
    for (int n = 0; n < NPTS; n++) mx = fmaxf(mx, base[(size_t)n * 512]);
    feat[b * 512 + o] = mx;
}

// ---------------- final linear: out[b,j] = sum_o feat[b,o]*We[j,o] ----------------
__global__ __launch_bounds__(256) void final_kernel(const float* __restrict__ We,
                                                    const float* __restrict__ feat,
                                                    float* __restrict__ out) {
    __shared__ float sf[BATCH * 512];
    int t = threadIdx.x;
    for (int i = t; i < BATCH * 512; i += 256) sf[i] = feat[i];
    __syncthreads();
    int j = t;  // 256 outputs
    float acc[BATCH] = {0.f, 0.f, 0.f, 0.f};
    for (int o = 0; o < 512; o++) {        // ascending, single accumulator
        float w = We[(size_t)j * 512 + o];
        #pragma unroll
        for (int b = 0; b < BATCH; b++) acc[b] = fmaf(sf[b * 512 + o], w, acc[b]);
    }
    #pragma unroll
    for (int b = 0; b < BATCH; b++) out[b * 256 + j] = acc[b];
}

// ---------------- host side ----------------
static void* sym_addr(const void* sym) { void* p; cudaGetSymbolAddress(&p, sym); return p; }

extern "C" void kernel_launch(void* const* d_in, const int* in_sizes, int n_in,
                              void* d_out, int out_size) {
    (void)in_sizes; (void)n_in; (void)out_size;
    const float* x = (const float*)d_in[0];
    const float* Wl[5] = { (const float*)d_in[1], (const float*)d_in[4],
                           (const float*)d_in[7], (const float*)d_in[10],
                           (const float*)d_in[13] };
    const float* gl[5] = { (const float*)d_in[2], (const float*)d_in[5],
                           (const float*)d_in[8], (const float*)d_in[11],
                           (const float*)d_in[14] };
    const float* bl[5] = { (const float*)d_in[3], (const float*)d_in[6],
                           (const float*)d_in[9], (const float*)d_in[12],
                           (const float*)d_in[15] };
    const float* We = (const float*)d_in[16];
    float* out = (float*)d_out;

    float* xc   = (float*)sym_addr(g_xc);
    float* ye   = (float*)sym_addr(g_ye);
    float* q    = (float*)sym_addr(g_q);
    float* sq   = (float*)sym_addr(g_sq);
    int*   idxp = (int*)sym_addr(g_idx);
    float* feat = (float*)sym_addr(g_feat);

    struct Layer { int C, O, colIn, colOut; };
    Layer L[4] = {
        {3,   64,  -1,  0},
        {64,  128,  0,  64},
        {128, 256, 64,  192},
        {256, 512, 192, 448},
    };

    for (int li = 0; li < 4; li++) {
        const float* X = (li == 0) ? x : (xc + L[li].colIn);
        int ld = (li == 0) ? 3 : 960;
        int C = L[li].C, O = L[li].O;

        if (C >= 64) {
            sqnorm_warp_kernel<<<(NROWS * 32 + 255) / 256, 256>>>(X, ld, C, sq);
        } else {
            sqnorm_kernel<<<(NROWS + 255) / 256, 256>>>(X, ld, C, sq);
        }
        knn_kernel<<<NROWS / 4, 256>>>(X, ld, C, sq, idxp);

        // edge conv (literal): ye[edge, o] = sum_{c=0}^{2C-1} e[edge,c]*W[o,c]
        {
            dim3 grid((O + BN_ - 1) / BN_, (NROWS * KNN) / BM);
            sgemm_kernel<<<grid, 256>>>(X, ld, Wl[li], 2 * C,
                                        ye, O, O, 2 * C, C,
                                        1, idxp, 0, nullptr, nullptr);
        }
        aggregate_kernel<<<NROWS, 256>>>(ye, O, gl[li], bl[li],
                                         xc + L[li].colOut);
    }

    // conv5: y = LReLU(BN(xc @ W5^T)) into q (ld=512)
    {
        dim3 grid(512 / BN_, NROWS / BM);
        sgemm_kernel<<<grid, 256>>>(xc, 960, Wl[4], 960,
                                    q, 512, 512, 960, 0,
                                    0, nullptr, 1, gl[4], bl[4]);
    }
    rowmax_kernel<<<BATCH, 512>>>(q, feat);
    final_kernel<<<1, 256>>>(We, feat, out);
}

// round 15
// speedup vs baseline: 1.2646x; 1.0382x over previous
#include <cuda_runtime.h>
#include <cfloat>
#include <cstddef>

#define BATCH 4
#define NPTS  1024
#define NROWS (BATCH*NPTS)
#define KNN   20
#define BNS   0.99999500003749968f   // 1/sqrt(1+1e-5)

// ---------------- scratch (static device globals; no allocation) ----------------
__device__ float g_xc[NROWS * 960];              // concat feature buffer [x1|x2|x3|x4]
__device__ float g_ye[NROWS * KNN * 512];        // per-edge conv output (ld = O)
__device__ float g_q[NROWS * 512];               // conv5 out
__device__ float g_sq[NROWS];                    // squared norms
__device__ int   g_idx[NROWS * KNN];             // knn indices (within-batch)
__device__ float g_feat[BATCH * 512];            // global max-pooled features

// ---------------- packed f32x2 FMA (two independent IEEE fp32 FMAs) --------------
__device__ __forceinline__ void ffma2(unsigned long long& d,
                                      unsigned long long a,
                                      unsigned long long b) {
    asm("fma.rn.f32x2 %0, %1, %2, %3;" : "=l"(d) : "l"(a), "l"(b), "l"(d));
}
__device__ __forceinline__ unsigned long long bcast2(float x) {
    unsigned long long r;
    unsigned xb = __float_as_uint(x);
    asm("mov.b64 %0, {%1, %1};" : "=l"(r) : "r"(xb));
    return r;
}

// orderable key for float (after -0 -> +0 canonicalization)
__device__ __forceinline__ unsigned ord32(float v) {
    unsigned b = __float_as_uint(__fadd_rn(v, 0.0f));   // -0 -> +0; else identity
    return (b & 0x80000000u) ? ~b : (b | 0x80000000u);
}

// ---------------- squared norms, small C: strict sequential (DO NOT CHANGE) -------
__global__ void sqnorm_kernel(const float* __restrict__ X, int ld, int C,
                              float* __restrict__ sq) {
    int i = blockIdx.x * blockDim.x + threadIdx.x;
    if (i >= NROWS) return;
    const float* r = X + (size_t)i * ld;
    float s = 0.f;
    for (int c = 0; c < C; c++) {
        float p = __fmul_rn(r[c], r[c]);
        s = __fadd_rn(s, p);
    }
    sq[i] = s;
}

// ---------------- squared norms, C>=64: XLA warp row-reduce (DO NOT CHANGE) -------
__global__ void sqnorm_warp_kernel(const float* __restrict__ X, int ld, int C,
                                   float* __restrict__ sq) {
    int gt = blockIdx.x * blockDim.x + threadIdx.x;
    int warp = gt >> 5;
    int lane = gt & 31;
    if (warp >= NROWS) return;
    const float* r = X + (size_t)warp * ld;
    float s = 0.f;
    for (int c = lane; c < C; c += 32) s = fmaf(r[c], r[c], s);
    #pragma unroll
    for (int off = 16; off > 0; off >>= 1)
        s = __fadd_rn(s, __shfl_down_sync(0xffffffffu, s, off));
    if (lane == 0) sq[warp] = s;
}

// ---------------- knn: 4 rows per block; distances identical to passing R12 -------
// Selection: composite keys key = (ord32(d)<<32)|(1023-m). Warp-local top-20
// (descending) then per-row 2-way sorted merge of the two 20-lists.
__global__ __launch_bounds__(256) void knn_kernel(const float* __restrict__ X,
                                                  int ld, int C,
                                                  const float* __restrict__ sq,
                                                  int* __restrict__ idx) {
    int row0 = blockIdx.x * 4;            // 4 consecutive rows, same batch
    int b = row0 >> 10;
    int n0r = row0 & 1023;
    const float* base = X + (size_t)b * NPTS * ld;

    __shared__ __align__(16) float ctr4[4][256];
    __shared__ float d4[4][NPTS];
    __shared__ unsigned long long wk[8][KNN];   // per-warp top-20 keys, descending

    int t = threadIdx.x;
    int lane = t & 31, warp = t >> 5;

    for (int rc = t; rc < 4 * C; rc += 256) {
        int r = rc / C, c = rc - r * C;
        ctr4[r][c] = base[(size_t)(n0r + r) * ld + c];
    }
    __syncthreads();

    float sqn[4];
    #pragma unroll
    for (int r = 0; r < 4; r++) sqn[r] = sq[row0 + r];

    if ((C & 3) == 0 && (ld & 3) == 0) {
        int C4 = C >> 2;
        const float4* xm[4];
        #pragma unroll
        for (int u = 0; u < 4; u++)
            xm[u] = (const float4*)(base + (size_t)(t + u * 256) * ld);

        float s[4][4];                    // [cand u][row r]
        #pragma unroll
        for (int u = 0; u < 4; u++)
            #pragma unroll
            for (int r = 0; r < 4; r++) s[u][r] = 0.f;

        for (int c = 0; c < C4; c++) {
            float4 v[4], uu[4];
            #pragma unroll
            for (int u = 0; u < 4; u++) v[u] = xm[u][c];
            #pragma unroll
            for (int r = 0; r < 4; r++) uu[r] = ((const float4*)ctr4[r])[c];
            #pragma unroll
            for (int u = 0; u < 4; u++)
                #pragma unroll
                for (int r = 0; r < 4; r++) {
                    s[u][r] = fmaf(v[u].x, uu[r].x, s[u][r]);
                    s[u][r] = fmaf(v[u].y, uu[r].y, s[u][r]);
                    s[u][r] = fmaf(v[u].z, uu[r].z, s[u][r]);
                    s[u][r] = fmaf(v[u].w, uu[r].w, s[u][r]);
                }
        }
        #pragma unroll
        for (int u = 0; u < 4; u++) {
            int m = t + u * 256;
            float sqm = sq[(b << 10) + m];
            #pragma unroll
            for (int r = 0; r < 4; r++) {
                float dd = __fmul_rn(2.0f, s[u][r]);
                dd = __fsub_rn(dd, sqn[r]);
                dd = __fsub_rn(dd, sqm);
                d4[r][m] = dd;
            }
        }
    } else {
        for (int u = 0; u < 4; u++) {
            int m = t + u * 256;
            const float* xmp = base + (size_t)m * ld;
            float sqm = sq[(b << 10) + m];
            for (int r = 0; r < 4; r++) {
                float s = 0.f;
                for (int c = 0; c < C; c++) {
                    float p = __fmul_rn(xmp[c], ctr4[r][c]);
                    s = __fadd_rn(s, p);
                }
                float dd = __fmul_rn(2.0f, s);
                dd = __fsub_rn(dd, sqn[r]);
                dd = __fsub_rn(dd, sqm);
                d4[r][m] = dd;
            }
        }
    }
    __syncthreads();

    // ---- warp-local top-20: warp w -> row (w>>1), half (w&1) = 512 candidates ----
    {
        int r = warp >> 1;
        int q = warp & 1;
        int mbase = (q << 9) + lane;     // m = mbase + 32*j, j=0..15

        unsigned long long key[16];
        #pragma unroll
        for (int j = 0; j < 16; j++) {
            int m = mbase + (j << 5);
            key[j] = ((unsigned long long)ord32(d4[r][m]) << 32)
                   | (unsigned)(NPTS - 1 - m);
        }
        unsigned alive = 0xFFFFu;

        unsigned long long bk = 0ull; int bj = -1;
        #pragma unroll
        for (int j = 0; j < 16; j++)
            if (key[j] > bk) { bk = key[j]; bj = j; }

        for (int rr = 0; rr < KNN; rr++) {
            unsigned long long mk = bk;
            #pragma unroll
            for (int off = 16; off > 0; off >>= 1) {
                unsigned long long ok = __shfl_down_sync(0xffffffffu, mk, off);
                if (ok > mk) mk = ok;
            }
            unsigned long long win = __shfl_sync(0xffffffffu, mk, 0);
            if (lane == 0) wk[warp][rr] = win;
            if (bk == win) {              // keys unique -> exactly one owner lane
                alive &= ~(1u << bj);
                bk = 0ull; bj = -1;
                #pragma unroll
                for (int j = 0; j < 16; j++)
                    if ((alive >> j) & 1u)
                        if (key[j] > bk) { bk = key[j]; bj = j; }
            }
        }
    }
    __syncthreads();

    // ---- per-row merge: two descending 20-lists -> global top-20 ----
    // 2-way sorted merge; one thread per row (t = 0..3). Keys are unique.
    if (t < 4) {
        int r = t;
        int row = row0 + r;
        const unsigned long long* A0 = wk[2 * r];
        const unsigned long long* A1 = wk[2 * r + 1];
        int i0 = 0, i1 = 0;
        #pragma unroll
        for (int rr = 0; rr < KNN; rr++) {
            unsigned long long ka = A0[i0];
            unsigned long long kb = A1[i1];
            unsigned long long win;
            if (ka > kb) { win = ka; i0++; } else { win = kb; i1++; }
            int m = (NPTS - 1) - (int)(unsigned)(win & 0xFFFFFFFFull);
            idx[row * KNN + rr] = m;
        }
    }
}

// ---------------- fp32 SGEMM via packed f32x2 FMA (UNCHANGED from passing R12) ---
#define BM 128
#define BN_ 128
#define BK 16

__global__ __launch_bounds__(256) void sgemm_kernel(
    const float* __restrict__ A, int lda,
    const float* __restrict__ Bw, int ldb,
    float* __restrict__ Cc, int ldc,
    int Nn, int Kk, int Chalf,
    int mode, const int* __restrict__ idx,
    int epi, const float* __restrict__ gs, const float* __restrict__ bs) {

    __shared__ __align__(16) float As[BK][BM + 4];
    __shared__ __align__(16) float Bs[BK][BN_ + 4];
    __shared__ int nbr_s[BM];
    __shared__ int ctr_s[BM];

    int t  = threadIdx.x;
    int tx = t & 15, ty = t >> 4;
    int m0 = blockIdx.y * BM;
    int n0 = blockIdx.x * BN_;

    if (mode == 1) {
        if (t < BM) {
            int edge = m0 + t;
            int row = edge / KNN;          // global point row 0..4095
            int b = row >> 10;
            nbr_s[t] = (b << 10) + idx[edge];
            ctr_s[t] = row;
        }
        __syncthreads();
    }

    unsigned long long acc2[8][4];        // [i][j-pair]; lanes = two fp32 chains
    #pragma unroll
    for (int i = 0; i < 8; i++)
        #pragma unroll
        for (int j = 0; j < 4; j++) acc2[i][j] = 0ull;

    int kTiles = (Kk + BK - 1) / BK;

    // ---- load tile 0 ----
    #pragma unroll
    for (int u = 0; u < 8; u++) {
        int e = t + u * 256;
        int i = e >> 4, k = e & 15;
        float v = 0.f;
        if (k < Kk) {
            if (mode == 1) {
                if (k < Chalf)
                    v = __fsub_rn(A[(size_t)nbr_s[i] * lda + k],
                                  A[(size_t)ctr_s[i] * lda + k]);
                else
                    v = A[(size_t)ctr_s[i] * lda + (k - Chalf)];
            } else {
                v = A[(size_t)(m0 + i) * lda + k];
            }
        }
        As[k][i] = v;
    }
    #pragma unroll
    for (int u = 0; u < 8; u++) {
        int e = t + u * 256;
        int j = e >> 4, k = e & 15;
        float v = 0.f;
        if (k < Kk && (n0 + j) < Nn)
            v = Bw[(size_t)(n0 + j) * ldb + k];
        Bs[k][j] = v;
    }
    __syncthreads();

    for (int kt = 0; kt < kTiles; kt++) {
        float pa[8], pb[8];
        bool more = (kt + 1 < kTiles);
        if (more) {
            int k0n = (kt + 1) * BK;
            #pragma unroll
            for (int u = 0; u < 8; u++) {
                int e = t + u * 256;
                int i = e >> 4, k = e & 15;
                int gk = k0n + k;
                float v = 0.f;
                if (gk < Kk) {
                    if (mode == 1) {
                        if (gk < Chalf)
                            v = __fsub_rn(A[(size_t)nbr_s[i] * lda + gk],
                                          A[(size_t)ctr_s[i] * lda + gk]);
                        else
                            v = A[(size_t)ctr_s[i] * lda + (gk - Chalf)];
                    } else {
                        v = A[(size_t)(m0 + i) * lda + gk];
                    }
                }
                pa[u] = v;
            }
            #pragma unroll
            for (int u = 0; u < 8; u++) {
                int e = t + u * 256;
                int j = e >> 4, k = e & 15;
                int gk = k0n + k;
                float v = 0.f;
                if (gk < Kk && (n0 + j) < Nn)
                    v = Bw[(size_t)(n0 + j) * ldb + gk];
                pb[u] = v;
            }
        }

        // ---- compute current tile (ascending k) ----
        #pragma unroll
        for (int k = 0; k < BK; k++) {
            float a[8];
            *(float4*)&a[0] = *(const float4*)&As[k][ty * 8];
            *(float4*)&a[4] = *(const float4*)&As[k][ty * 8 + 4];
            ulonglong2 bb0 = *(const ulonglong2*)&Bs[k][tx * 8];
            ulonglong2 bb1 = *(const ulonglong2*)&Bs[k][tx * 8 + 4];
            unsigned long long b2[4] = { bb0.x, bb0.y, bb1.x, bb1.y };
            #pragma unroll
            for (int i = 0; i < 8; i++) {
                unsigned long long aa = bcast2(a[i]);
                #pragma unroll
                for (int j = 0; j < 4; j++) ffma2(acc2[i][j], aa, b2[j]);
            }
        }
        __syncthreads();

        if (more) {
            #pragma unroll
            for (int u = 0; u < 8; u++) {
                int e = t + u * 256;
                int i = e >> 4, k = e & 15;
                As[k][i] = pa[u];
            }
            #pragma unroll
            for (int u = 0; u < 8; u++) {
                int e = t + u * 256;
                int j = e >> 4, k = e & 15;
                Bs[k][j] = pb[u];
            }
            __syncthreads();
        }
    }

    #pragma unroll
    for (int i = 0; i < 8; i++) {
        int m = m0 + ty * 8 + i;
        #pragma unroll
        for (int j2 = 0; j2 < 4; j2++) {
            unsigned long long p = acc2[i][j2];
            float lo = __uint_as_float((unsigned)(p & 0xffffffffull));
            float hi = __uint_as_float((unsigned)(p >> 32));
            #pragma unroll
            for (int h = 0; h < 2; h++) {
                int n = n0 + tx * 8 + 2 * j2 + h;
                if (n < Nn) {
                    float v = h ? hi : lo;
                    if (epi) {
                        float gb = __fmul_rn(gs[n], BNS);
                        v = __fadd_rn(__fmul_rn(v, gb), bs[n]);
                        v = v > 0.f ? v : __fmul_rn(0.2f, v);
                    }
                    Cc[(size_t)m * ldc + n] = v;
                }
            }
        }
    }
}

// ---------------- BN + LReLU + max over k (on edge conv outputs) ----------------
__global__ __launch_bounds__(256) void aggregate_kernel(
    const float* __restrict__ ye,   // [NROWS*KNN, O]
    int O,
    const float* __restrict__ gsc, const float* __restrict__ bia,
    float* __restrict__ outc) {     // xc + colOut, ld 960

    int row = blockIdx.x;
    int t = threadIdx.x;
    const float* yrow = ye + (size_t)row * KNN * O;

    for (int o = t; o < O; o += 256) {
        float gb = __fmul_rn(gsc[o], BNS);
        float bo = bia[o];
        float mx = -FLT_MAX;
        #pragma unroll
        for (int k = 0; k < KNN; k++) {
            float v = yrow[(size_t)k * O + o];
            v = __fadd_rn(__fmul_rn(v, gb), bo);
            v = v > 0.f ? v : __fmul_rn(0.2f, v);
            mx = fmaxf(mx, v);
        }
        outc[(size_t)row * 960 + o] = mx;
    }
}

// ---------------- global max-pool over N ----------------
__global__ void rowmax_kernel(const float* __restrict__ y, float* __restrict__ feat) {
    int b = blockIdx.x;
    int o = threadIdx.x;  // 512 threads
    float mx = -FLT_MAX;
    const float* base = y + (size_t)b * NPTS * 512 + o;
    for (int n = 0; n < NPTS; n++) mx = fmaxf(mx, base[(size_t)n * 512]);
    feat[b * 512 + o] = mx;
}

// ---------------- final linear: out[b,j] = sum_o feat[b,o]*We[j,o] ----------------
__global__ __launch_bounds__(256) void final_kernel(const float* __restrict__ We,
                                                    const float* __restrict__ feat,
                                                    float* __restrict__ out) {
    __shared__ float sf[BATCH * 512];
    int t = threadIdx.x;
    for (int i = t; i < BATCH * 512; i += 256) sf[i] = feat[i];
    __syncthreads();
    int j = t;  // 256 outputs
    float acc[BATCH] = {0.f, 0.f, 0.f, 0.f};
    for (int o = 0; o < 512; o++) {        // ascending, single accumulator
        float w = We[(size_t)j * 512 + o];
        #pragma unroll
        for (int b = 0; b < BATCH; b++) acc[b] = fmaf(sf[b * 512 + o], w, acc[b]);
    }
    #pragma unroll
    for (int b = 0; b < BATCH; b++) out[b * 256 + j] = acc[b];
}

// ---------------- host side ----------------
static void* sym_addr(const void* sym) { void* p; cudaGetSymbolAddress(&p, sym); return p; }

extern "C" void kernel_launch(void* const* d_in, const int* in_sizes, int n_in,
                              void* d_out, int out_size) {
    (void)in_sizes; (void)n_in; (void)out_size;
    const float* x = (const float*)d_in[0];
    const float* Wl[5] = { (const float*)d_in[1], (const float*)d_in[4],
                           (const float*)d_in[7], (const float*)d_in[10],
                           (const float*)d_in[13] };
    const float* gl[5] = { (const float*)d_in[2], (const float*)d_in[5],
                           (const float*)d_in[8], (const float*)d_in[11],
                           (const float*)d_in[14] };
    const float* bl[5] = { (const float*)d_in[3], (const float*)d_in[6],
                           (const float*)d_in[9], (const float*)d_in[12],
                           (const float*)d_in[15] };
    const float* We = (const float*)d_in[16];
    float* out = (float*)d_out;

    float* xc   = (float*)sym_addr(g_xc);
    float* ye   = (float*)sym_addr(g_ye);
    float* q    = (float*)sym_addr(g_q);
    float* sq   = (float*)sym_addr(g_sq);
    int*   idxp = (int*)sym_addr(g_idx);
    float* feat = (float*)sym_addr(g_feat);

    struct Layer { int C, O, colIn, colOut; };
    Layer L[4] = {
        {3,   64,  -1,  0},
        {64,  128,  0,  64},
        {128, 256, 64,  192},
        {256, 512, 192, 448},
    };

    for (int li = 0; li < 4; li++) {
        const float* X = (li == 0) ? x : (xc + L[li].colIn);
        int ld = (li == 0) ? 3 : 960;
        int C = L[li].C, O = L[li].O;

        if (C >= 64) {
            sqnorm_warp_kernel<<<(NROWS * 32 + 255) / 256, 256>>>(X, ld, C, sq);
        } else {
            sqnorm_kernel<<<(NROWS + 255) / 256, 256>>>(X, ld, C, sq);
        }
        knn_kernel<<<NROWS / 4, 256>>>(X, ld, C, sq, idxp);

        // edge conv (literal): ye[edge, o] = sum_{c=0}^{2C-1} e[edge,c]*W[o,c]
        {
            dim3 grid((O + BN_ - 1) / BN_, (NROWS * KNN) / BM);
            sgemm_kernel<<<grid, 256>>>(X, ld, Wl[li], 2 * C,
                                        ye, O, O, 2 * C, C,
                                        1, idxp, 0, nullptr, nullptr);
        }
        aggregate_kernel<<<NROWS, 256>>>(ye, O, gl[li], bl[li],
                                         xc + L[li].colOut);
    }

    // conv5: y = LReLU(BN(xc @ W5^T)) into q (ld=512)
    {
        dim3 grid(512 / BN_, NROWS / BM);
        sgemm_kernel<<<grid, 256>>>(xc, 960, Wl[4], 960,
                                    q, 512, 512, 960, 0,
                                    0, nullptr, 1, gl[4], bl[4]);
    }
    rowmax_kernel<<<BATCH, 512>>>(q, feat);
    final_kernel<<<1, 256>>>(We, feat, out);
}

// round 17
// speedup vs baseline: 1.5934x; 1.2600x over previous
#include <cuda_runtime.h>
#include <cfloat>
#include <cstddef>

#define BATCH 4
#define NPTS  1024
#define NROWS (BATCH*NPTS)
#define KNN   20
#define BNS   0.99999500003749968f   // 1/sqrt(1+1e-5)

// ---------------- scratch (static device globals; no allocation) ----------------
__device__ float g_xc[NROWS * 960];              // concat feature buffer [x1|x2|x3|x4]
__device__ float g_ye[NROWS * KNN * 512];        // per-edge conv output (ld = O)
__device__ float g_q[NROWS * 512];               // conv5 out
__device__ float g_sq[NROWS];                    // squared norms
__device__ int   g_idx[NROWS * KNN];             // knn indices (within-batch)
__device__ float g_feat[BATCH * 512];            // global max-pooled features

// ---------------- packed f32x2 FMA (two independent IEEE fp32 FMAs) --------------
__device__ __forceinline__ void ffma2(unsigned long long& d,
                                      unsigned long long a,
                                      unsigned long long b) {
    asm("fma.rn.f32x2 %0, %1, %2, %3;" : "=l"(d) : "l"(a), "l"(b), "l"(d));
}
__device__ __forceinline__ unsigned long long bcast2(float x) {
    unsigned long long r;
    unsigned xb = __float_as_uint(x);
    asm("mov.b64 %0, {%1, %1};" : "=l"(r) : "r"(xb));
    return r;
}

// orderable key for float (after -0 -> +0 canonicalization)
__device__ __forceinline__ unsigned ord32(float v) {
    unsigned b = __float_as_uint(__fadd_rn(v, 0.0f));   // -0 -> +0; else identity
    return (b & 0x80000000u) ? ~b : (b | 0x80000000u);
}

// ---------------- squared norms, small C: strict sequential (DO NOT CHANGE) -------
__global__ void sqnorm_kernel(const float* __restrict__ X, int ld, int C,
                              float* __restrict__ sq) {
    int i = blockIdx.x * blockDim.x + threadIdx.x;
    if (i >= NROWS) return;
    const float* r = X + (size_t)i * ld;
    float s = 0.f;
    for (int c = 0; c < C; c++) {
        float p = __fmul_rn(r[c], r[c]);
        s = __fadd_rn(s, p);
    }
    sq[i] = s;
}

// ---------------- squared norms, C>=64: XLA warp row-reduce (DO NOT CHANGE) -------
__global__ void sqnorm_warp_kernel(const float* __restrict__ X, int ld, int C,
                                   float* __restrict__ sq) {
    int gt = blockIdx.x * blockDim.x + threadIdx.x;
    int warp = gt >> 5;
    int lane = gt & 31;
    if (warp >= NROWS) return;
    const float* r = X + (size_t)warp * ld;
    float s = 0.f;
    for (int c = lane; c < C; c += 32) s = fmaf(r[c], r[c], s);
    #pragma unroll
    for (int off = 16; off > 0; off >>= 1)
        s = __fadd_rn(s, __shfl_down_sync(0xffffffffu, s, off));
    if (lane == 0) sq[warp] = s;
}

// ---------------- knn: 4 rows per block; distances identical to passing R14 -------
__global__ __launch_bounds__(256) void knn_kernel(const float* __restrict__ X,
                                                  int ld, int C,
                                                  const float* __restrict__ sq,
                                                  int* __restrict__ idx) {
    int row0 = blockIdx.x * 4;            // 4 consecutive rows, same batch
    int b = row0 >> 10;
    int n0r = row0 & 1023;
    const float* base = X + (size_t)b * NPTS * ld;

    __shared__ __align__(16) float ctr4[4][256];
    __shared__ float d4[4][NPTS];
    __shared__ unsigned long long wk[8][KNN];   // per-warp top-20 keys, descending

    int t = threadIdx.x;
    int lane = t & 31, warp = t >> 5;

    for (int rc = t; rc < 4 * C; rc += 256) {
        int r = rc / C, c = rc - r * C;
        ctr4[r][c] = base[(size_t)(n0r + r) * ld + c];
    }
    __syncthreads();

    float sqn[4];
    #pragma unroll
    for (int r = 0; r < 4; r++) sqn[r] = sq[row0 + r];

    if ((C & 3) == 0 && (ld & 3) == 0) {
        int C4 = C >> 2;
        const float4* xm[4];
        #pragma unroll
        for (int u = 0; u < 4; u++)
            xm[u] = (const float4*)(base + (size_t)(t + u * 256) * ld);

        float s[4][4];                    // [cand u][row r]
        #pragma unroll
        for (int u = 0; u < 4; u++)
            #pragma unroll
            for (int r = 0; r < 4; r++) s[u][r] = 0.f;

        for (int c = 0; c < C4; c++) {
            float4 v[4], uu[4];
            #pragma unroll
            for (int u = 0; u < 4; u++) v[u] = xm[u][c];
            #pragma unroll
            for (int r = 0; r < 4; r++) uu[r] = ((const float4*)ctr4[r])[c];
            #pragma unroll
            for (int u = 0; u < 4; u++)
                #pragma unroll
                for (int r = 0; r < 4; r++) {
                    s[u][r] = fmaf(v[u].x, uu[r].x, s[u][r]);
                    s[u][r] = fmaf(v[u].y, uu[r].y, s[u][r]);
                    s[u][r] = fmaf(v[u].z, uu[r].z, s[u][r]);
                    s[u][r] = fmaf(v[u].w, uu[r].w, s[u][r]);
                }
        }
        #pragma unroll
        for (int u = 0; u < 4; u++) {
            int m = t + u * 256;
            float sqm = sq[(b << 10) + m];
            #pragma unroll
            for (int r = 0; r < 4; r++) {
                float dd = __fmul_rn(2.0f, s[u][r]);
                dd = __fsub_rn(dd, sqn[r]);
                dd = __fsub_rn(dd, sqm);
                d4[r][m] = dd;
            }
        }
    } else {
        for (int u = 0; u < 4; u++) {
            int m = t + u * 256;
            const float* xmp = base + (size_t)m * ld;
            float sqm = sq[(b << 10) + m];
            for (int r = 0; r < 4; r++) {
                float s = 0.f;
                for (int c = 0; c < C; c++) {
                    float p = __fmul_rn(xmp[c], ctr4[r][c]);
                    s = __fadd_rn(s, p);
                }
                float dd = __fmul_rn(2.0f, s);
                dd = __fsub_rn(dd, sqn[r]);
                dd = __fsub_rn(dd, sqm);
                d4[r][m] = dd;
            }
        }
    }
    __syncthreads();

    // ---- warp-local top-20: warp w -> row (w>>1), half (w&1) = 512 candidates ----
    {
        int r = warp >> 1;
        int q = warp & 1;
        int mbase = (q << 9) + lane;     // m = mbase + 32*j, j=0..15

        unsigned long long key[16];
        #pragma unroll
        for (int j = 0; j < 16; j++) {
            int m = mbase + (j << 5);
            key[j] = ((unsigned long long)ord32(d4[r][m]) << 32)
                   | (unsigned)(NPTS - 1 - m);
        }
        unsigned alive = 0xFFFFu;

        unsigned long long bk = 0ull; int bj = -1;
        #pragma unroll
        for (int j = 0; j < 16; j++)
            if (key[j] > bk) { bk = key[j]; bj = j; }

        for (int rr = 0; rr < KNN; rr++) {
            unsigned long long mk = bk;
            #pragma unroll
            for (int off = 16; off > 0; off >>= 1) {
                unsigned long long ok = __shfl_down_sync(0xffffffffu, mk, off);
                if (ok > mk) mk = ok;
            }
            unsigned long long win = __shfl_sync(0xffffffffu, mk, 0);
            if (lane == 0) wk[warp][rr] = win;
            if (bk == win) {              // keys unique -> exactly one owner lane
                alive &= ~(1u << bj);
                bk = 0ull; bj = -1;
                #pragma unroll
                for (int j = 0; j < 16; j++)
                    if ((alive >> j) & 1u)
                        if (key[j] > bk) { bk = key[j]; bj = j; }
            }
        }
    }
    __syncthreads();

    // ---- per-row merge: two descending 20-lists -> global top-20 ----
    if (t < 4) {
        int r = t;
        int row = row0 + r;
        const unsigned long long* A0 = wk[2 * r];
        const unsigned long long* A1 = wk[2 * r + 1];
        int i0 = 0, i1 = 0;
        #pragma unroll
        for (int rr = 0; rr < KNN; rr++) {
            unsigned long long ka = A0[i0];
            unsigned long long kb = A1[i1];
            unsigned long long win;
            if (ka > kb) { win = ka; i0++; } else { win = kb; i1++; }
            int m = (NPTS - 1) - (int)(unsigned)(win & 0xFFFFFFFFull);
            idx[row * KNN + rr] = m;
        }
    }
}

// ---------------- fp32 SGEMM via packed f32x2 FMA --------------------------------
// Numerics identical to passing R14. NEW: __launch_bounds__(256, 2) caps regs at
// 128 so TWO blocks co-reside per SM — one block's FFMA2 stream covers the other's
// sync/prefetch bubbles.
#define BM 128
#define BN_ 128
#define BK 16

__global__ __launch_bounds__(256, 2) void sgemm_kernel(
    const float* __restrict__ A, int lda,
    const float* __restrict__ Bw, int ldb,
    float* __restrict__ Cc, int ldc,
    int Nn, int Kk, int Chalf,
    int mode, const int* __restrict__ idx,
    int epi, const float* __restrict__ gs, const float* __restrict__ bs) {

    __shared__ __align__(16) float As[BK][BM + 4];
    __shared__ __align__(16) float Bs[BK][BN_ + 4];
    __shared__ int nbr_s[BM];
    __shared__ int ctr_s[BM];

    int t  = threadIdx.x;
    int tx = t & 15, ty = t >> 4;
    int m0 = blockIdx.y * BM;
    int n0 = blockIdx.x * BN_;

    if (mode == 1) {
        if (t < BM) {
            int edge = m0 + t;
            int row = edge / KNN;          // global point row 0..4095
            int b = row >> 10;
            nbr_s[t] = (b << 10) + idx[edge];
            ctr_s[t] = row;
        }
        __syncthreads();
    }

    unsigned long long acc2[8][4];        // [i][j-pair]; lanes = two fp32 chains
    #pragma unroll
    for (int i = 0; i < 8; i++)
        #pragma unroll
        for (int j = 0; j < 4; j++) acc2[i][j] = 0ull;

    int kTiles = (Kk + BK - 1) / BK;

    // ---- load tile 0 ----
    #pragma unroll
    for (int u = 0; u < 8; u++) {
        int e = t + u * 256;
        int i = e >> 4, k = e & 15;
        float v = 0.f;
        if (k < Kk) {
            if (mode == 1) {
                if (k < Chalf)
                    v = __fsub_rn(A[(size_t)nbr_s[i] * lda + k],
                                  A[(size_t)ctr_s[i] * lda + k]);
                else
                    v = A[(size_t)ctr_s[i] * lda + (k - Chalf)];
            } else {
                v = A[(size_t)(m0 + i) * lda + k];
            }
        }
        As[k][i] = v;
    }
    #pragma unroll
    for (int u = 0; u < 8; u++) {
        int e = t + u * 256;
        int j = e >> 4, k = e & 15;
        float v = 0.f;
        if (k < Kk && (n0 + j) < Nn)
            v = Bw[(size_t)(n0 + j) * ldb + k];
        Bs[k][j] = v;
    }
    __syncthreads();

    for (int kt = 0; kt < kTiles; kt++) {
        float pa[8], pb[8];
        bool more = (kt + 1 < kTiles);
        if (more) {
            int k0n = (kt + 1) * BK;
            #pragma unroll
            for (int u = 0; u < 8; u++) {
                int e = t + u * 256;
                int i = e >> 4, k = e & 15;
                int gk = k0n + k;
                float v = 0.f;
                if (gk < Kk) {
                    if (mode == 1) {
                        if (gk < Chalf)
                            v = __fsub_rn(A[(size_t)nbr_s[i] * lda + gk],
                                          A[(size_t)ctr_s[i] * lda + gk]);
                        else
                            v = A[(size_t)ctr_s[i] * lda + (gk - Chalf)];
                    } else {
                        v = A[(size_t)(m0 + i) * lda + gk];
                    }
                }
                pa[u] = v;
            }
            #pragma unroll
            for (int u = 0; u < 8; u++) {
                int e = t + u * 256;
                int j = e >> 4, k = e & 15;
                int gk = k0n + k;
                float v = 0.f;
                if (gk < Kk && (n0 + j) < Nn)
                    v = Bw[(size_t)(n0 + j) * ldb + gk];
                pb[u] = v;
            }
        }

        // ---- compute current tile (ascending k) ----
        #pragma unroll
        for (int k = 0; k < BK; k++) {
            float a[8];
            *(float4*)&a[0] = *(const float4*)&As[k][ty * 8];
            *(float4*)&a[4] = *(const float4*)&As[k][ty * 8 + 4];
            ulonglong2 bb0 = *(const ulonglong2*)&Bs[k][tx * 8];
            ulonglong2 bb1 = *(const ulonglong2*)&Bs[k][tx * 8 + 4];
            unsigned long long b2[4] = { bb0.x, bb0.y, bb1.x, bb1.y };
            #pragma unroll
            for (int i = 0; i < 8; i++) {
                unsigned long long aa = bcast2(a[i]);
                #pragma unroll
                for (int j = 0; j < 4; j++) ffma2(acc2[i][j], aa, b2[j]);
            }
        }
        __syncthreads();

        if (more) {
            #pragma unroll
            for (int u = 0; u < 8; u++) {
                int e = t + u * 256;
                int i = e >> 4, k = e & 15;
                As[k][i] = pa[u];
            }
            #pragma unroll
            for (int u = 0; u < 8; u++) {
                int e = t + u * 256;
                int j = e >> 4, k = e & 15;
                Bs[k][j] = pb[u];
            }
            __syncthreads();
        }
    }

    #pragma unroll
    for (int i = 0; i < 8; i++) {
        int m = m0 + ty * 8 + i;
        #pragma unroll
        for (int j2 = 0; j2 < 4; j2++) {
            unsigned long long p = acc2[i][j2];
            float lo = __uint_as_float((unsigned)(p & 0xffffffffull));
            float hi = __uint_as_float((unsigned)(p >> 32));
            #pragma unroll
            for (int h = 0; h < 2; h++) {
                int n = n0 + tx * 8 + 2 * j2 + h;
                if (n < Nn) {
                    float v = h ? hi : lo;
                    if (epi) {
                        float gb = __fmul_rn(gs[n], BNS);
                        v = __fadd_rn(__fmul_rn(v, gb), bs[n]);
                        v = v > 0.f ? v : __fmul_rn(0.2f, v);
                    }
                    Cc[(size_t)m * ldc + n] = v;
                }
            }
        }
    }
}

// ---------------- BN + LReLU + max over k (on edge conv outputs) ----------------
__global__ __launch_bounds__(256) void aggregate_kernel(
    const float* __restrict__ ye,   // [NROWS*KNN, O]
    int O,
    const float* __restrict__ gsc, const float* __restrict__ bia,
    float* __restrict__ outc) {     // xc + colOut, ld 960

    int row = blockIdx.x;
    int t = threadIdx.x;
    const float* yrow = ye + (size_t)row * KNN * O;

    for (int o = t; o < O; o += 256) {
        float gb = __fmul_rn(gsc[o], BNS);
        float bo = bia[o];
        float mx = -FLT_MAX;
        #pragma unroll
        for (int k = 0; k < KNN; k++) {
            float v = yrow[(size_t)k * O + o];
            v = __fadd_rn(__fmul_rn(v, gb), bo);
            v = v > 0.f ? v : __fmul_rn(0.2f, v);
            mx = fmaxf(mx, v);
        }
        outc[(size_t)row * 960 + o] = mx;
    }
}

// ---------------- global max-pool over N ----------------
__global__ void rowmax_kernel(const float* __restrict__ y, float* __restrict__ feat) {
    int b = blockIdx.x;
    int o = threadIdx.x;  // 512 threads
    float mx = -FLT_MAX;
    const float* base = y + (size_t)b * NPTS * 512 + o;
    for (int n = 0; n < NPTS; n++) mx = fmaxf(mx, base[(size_t)n * 512]);
    feat[b * 512 + o] = mx;
}

// ---------------- final linear: out[b,j] = sum_o feat[b,o]*We[j,o] ----------------
__global__ __launch_bounds__(256) void final_kernel(const float* __restrict__ We,
                                                    const float* __restrict__ feat,
                                                    float* __restrict__ out) {
    __shared__ float sf[BATCH * 512];
    int t = threadIdx.x;
    for (int i = t; i < BATCH * 512; i += 256) sf[i] = feat[i];
    __syncthreads();
    int j = t;  // 256 outputs
    float acc[BATCH] = {0.f, 0.f, 0.f, 0.f};
    for (int o = 0; o < 512; o++) {        // ascending, single accumulator
        float w = We[(size_t)j * 512 + o];
        #pragma unroll
        for (int b = 0; b < BATCH; b++) acc[b] = fmaf(sf[b * 512 + o], w, acc[b]);
    }
    #pragma unroll
    for (int b = 0; b < BATCH; b++) out[b * 256 + j] = acc[b];
}

// ---------------- host side ----------------
static void* sym_addr(const void* sym) { void* p; cudaGetSymbolAddress(&p, sym); return p; }

extern "C" void kernel_launch(void* const* d_in, const int* in_sizes, int n_in,
                              void* d_out, int out_size) {
    (void)in_sizes; (void)n_in; (void)out_size;
    const float* x = (const float*)d_in[0];
    const float* Wl[5] = { (const float*)d_in[1], (const float*)d_in[4],
                           (const float*)d_in[7], (const float*)d_in[10],
                           (const float*)d_in[13] };
    const float* gl[5] = { (const float*)d_in[2], (const float*)d_in[5],
                           (const float*)d_in[8], (const float*)d_in[11],
                           (const float*)d_in[14] };
    const float* bl[5] = { (const float*)d_in[3], (const float*)d_in[6],
                           (const float*)d_in[9], (const float*)d_in[12],
                           (const float*)d_in[15] };
    const float* We = (const float*)d_in[16];
    float* out = (float*)d_out;

    float* xc   = (float*)sym_addr(g_xc);
    float* ye   = (float*)sym_addr(g_ye);
    float* q    = (float*)sym_addr(g_q);
    float* sq   = (float*)sym_addr(g_sq);
    int*   idxp = (int*)sym_addr(g_idx);
    float* feat = (float*)sym_addr(g_feat);

    struct Layer { int C, O, colIn, colOut; };
    Layer L[4] = {
        {3,   64,  -1,  0},
        {64,  128,  0,  64},
        {128, 256, 64,  192},
        {256, 512, 192, 448},
    };

    for (int li = 0; li < 4; li++) {
        const float* X = (li == 0) ? x : (xc + L[li].colIn);
        int ld = (li == 0) ? 3 : 960;
        int C = L[li].C, O = L[li].O;

        if (C >= 64) {
            sqnorm_warp_kernel<<<(NROWS * 32 + 255) / 256, 256>>>(X, ld, C, sq);
        } else {
            sqnorm_kernel<<<(NROWS + 255) / 256, 256>>>(X, ld, C, sq);
        }
        knn_kernel<<<NROWS / 4, 256>>>(X, ld, C, sq, idxp);

        // edge conv (literal): ye[edge, o] = sum_{c=0}^{2C-1} e[edge,c]*W[o,c]
        {
            dim3 grid((O + BN_ - 1) / BN_, (NROWS * KNN) / BM);
            sgemm_kernel<<<grid, 256>>>(X, ld, Wl[li], 2 * C,
                                        ye, O, O, 2 * C, C,
                                        1, idxp, 0, nullptr, nullptr);
        }
        aggregate_kernel<<<NROWS, 256>>>(ye, O, gl[li], bl[li],
                                         xc + L[li].colOut);
    }

    // conv5: y = LReLU(BN(xc @ W5^T)) into q (ld=512)
    {
        dim3 grid(512 / BN_, NROWS / BM);
        sgemm_kernel<<<grid, 256>>>(xc, 960, Wl[4], 960,
                                    q, 512, 512, 960, 0,
                                    0, nullptr, 1, gl[4], bl[4]);
    }
    rowmax_kernel<<<BATCH, 512>>>(q, feat);
    final_kernel<<<1, 256>>>(We, feat, out);
}